// round 7
// baseline (speedup 1.0000x reference)
#include <cuda_runtime.h>
#include <math.h>

#define BSZ 16
#define SEQ 2048
#define HID 1024
#define NSP_PER_B 32
#define NCLS 8
#define NLBL 3
#define NSPAN (BSZ * NSP_PER_B)   // 512
#define H4 (HID / 4)              // 256
#define CHUNKS 4
#define NGRID (NSPAN * CHUNKS)    // 2048

__device__ float g_partial[NGRID * NLBL];   // rewritten every launch
__device__ int   g_ticket = 0;              // reset by last CTA each launch

// Each CTA: pool ~16 rows of one span over H, dot with W[c] -> 3-float partial,
// publish via release-ticket. Last CTA of the grid combines all partials into
// logits and computes the masked-mean NLL. Single launch, no SC fences.
__global__ __launch_bounds__(256, 6)
void fused_kernel(const float* __restrict__ enc,
                  const float* __restrict__ W,
                  const float* __restrict__ bias,
                  const int* __restrict__ head,
                  const int* __restrict__ tail,
                  const int* __restrict__ cls,
                  const int* __restrict__ labels,
                  float* __restrict__ out,       // [NSPAN*NLBL] logits, then loss
                  int write_loss)
{
    const int span  = blockIdx.x >> 2;          // 0..511
    const int chunk = blockIdx.x & 3;           // 0..3
    const int b     = span / NSP_PER_B;
    const int s0    = head[span] + 1;
    const int n     = tail[span] - s0;          // full span length
    const int c     = cls[span];
    const int tid   = threadIdx.x;              // 256 threads, 1 float4 col each

    const int lo = (n * chunk) >> 2;
    const int hi = (n * (chunk + 1)) >> 2;
    const int m  = hi - lo;                     // rows in this chunk (~15-17)

    const float4* base = reinterpret_cast<const float4*>(enc)
                       + ((long)b * SEQ + s0 + lo) * H4 + tid;

    float4 acc = make_float4(0.f, 0.f, 0.f, 0.f);
    int s = 0;
    for (; s + 4 <= m; s += 4) {
        float4 v0 = base[(s + 0) * H4];
        float4 v1 = base[(s + 1) * H4];
        float4 v2 = base[(s + 2) * H4];
        float4 v3 = base[(s + 3) * H4];
        float x01 = v0.x + v1.x, x23 = v2.x + v3.x;
        float y01 = v0.y + v1.y, y23 = v2.y + v3.y;
        float z01 = v0.z + v1.z, z23 = v2.z + v3.z;
        float w01 = v0.w + v1.w, w23 = v2.w + v3.w;
        acc.x += x01 + x23;
        acc.y += y01 + y23;
        acc.z += z01 + z23;
        acc.w += w01 + w23;
    }
    for (; s < m; ++s) {
        float4 v = base[s * H4];
        acc.x += v.x; acc.y += v.y; acc.z += v.z; acc.w += v.w;
    }

    // W is (C, H, L): this thread's 4 H-cols are 12 contiguous floats.
    const float4* w4 = reinterpret_cast<const float4*>(W + (long)c * HID * NLBL)
                     + tid * 3;
    float4 w0 = w4[0], w1 = w4[1], w2 = w4[2];
    float p0 = acc.x * w0.x + acc.y * w0.w + acc.z * w1.z + acc.w * w2.y;
    float p1 = acc.x * w0.y + acc.y * w1.x + acc.z * w1.w + acc.w * w2.z;
    float p2 = acc.x * w0.z + acc.y * w1.y + acc.z * w2.x + acc.w * w2.w;

    #pragma unroll
    for (int off = 16; off > 0; off >>= 1) {
        p0 += __shfl_down_sync(0xffffffffu, p0, off);
        p1 += __shfl_down_sync(0xffffffffu, p1, off);
        p2 += __shfl_down_sync(0xffffffffu, p2, off);
    }
    __shared__ float sm[3][8];
    const int warp = tid >> 5, lane = tid & 31;
    if (lane == 0) { sm[0][warp] = p0; sm[1][warp] = p1; sm[2][warp] = p2; }
    __syncthreads();

    __shared__ int s_last;
    if (tid == 0) {
        float t0 = 0.f, t1 = 0.f, t2 = 0.f;
        #pragma unroll
        for (int w = 0; w < 8; ++w) { t0 += sm[0][w]; t1 += sm[1][w]; t2 += sm[2][w]; }
        g_partial[blockIdx.x * NLBL + 0] = t0;
        g_partial[blockIdx.x * NLBL + 1] = t1;
        g_partial[blockIdx.x * NLBL + 2] = t2;
        // Release-ticket: orders the STGs above to gpu scope without any
        // CCTL.IVALL-emitting SC fence. acq_rel so the last CTA also acquires.
        int t;
        asm volatile("atom.acq_rel.gpu.global.add.s32 %0, [%1], 1;"
                     : "=r"(t) : "l"(&g_ticket) : "memory");
        s_last = (t == NGRID - 1);
    }
    __syncthreads();

    if (!s_last) return;

    // ---- last CTA: combine 4 partials/span -> logits, masked-mean NLL ----
    float tn = 0.f, tv = 0.f;
    #pragma unroll
    for (int r = 0; r < 2; ++r) {
        int i = tid + r * 256;                  // span index
        const float* gp = g_partial + (i * CHUNKS) * NLBL;
        // ld.cg: bypass L1, read the release-ordered values from L2.
        float q0 = __ldcg(gp + 0), q1 = __ldcg(gp + 1),  q2  = __ldcg(gp + 2);
        float q3 = __ldcg(gp + 3), q4 = __ldcg(gp + 4),  q5  = __ldcg(gp + 5);
        float q6 = __ldcg(gp + 6), q7 = __ldcg(gp + 7),  q8  = __ldcg(gp + 8);
        float q9 = __ldcg(gp + 9), q10 = __ldcg(gp + 10), q11 = __ldcg(gp + 11);
        int ci = cls[i];
        float inv = 1.0f / (float)(tail[i] - head[i] - 1);
        float l0 = (q0 + q3 + q6 + q9)  * inv + bias[ci * NLBL + 0];
        float l1 = (q1 + q4 + q7 + q10) * inv + bias[ci * NLBL + 1];
        float l2 = (q2 + q5 + q8 + q11) * inv + bias[ci * NLBL + 2];
        out[i * NLBL + 0] = l0;
        out[i * NLBL + 1] = l1;
        out[i * NLBL + 2] = l2;
        int lab = labels[i];
        if (lab >= 0) {
            float mx  = fmaxf(l0, fmaxf(l1, l2));
            float lse = mx + logf(expf(l0 - mx) + expf(l1 - mx) + expf(l2 - mx));
            float lv  = (lab == 0) ? l0 : ((lab == 1) ? l1 : l2);
            tn += lse - lv;
            tv += 1.f;
        }
    }
    #pragma unroll
    for (int off = 16; off > 0; off >>= 1) {
        tn += __shfl_down_sync(0xffffffffu, tn, off);
        tv += __shfl_down_sync(0xffffffffu, tv, off);
    }
    __shared__ float sn[8], sv[8];
    if (lane == 0) { sn[warp] = tn; sv[warp] = tv; }
    __syncthreads();
    if (tid == 0) {
        float fn = 0.f, fv = 0.f;
        #pragma unroll
        for (int w = 0; w < 8; ++w) { fn += sn[w]; fv += sv[w]; }
        if (write_loss) out[NSPAN * NLBL] = fn / fv;
        g_ticket = 0;                           // reset for next graph replay
    }
}

extern "C" void kernel_launch(void* const* d_in, const int* in_sizes, int n_in,
                              void* d_out, int out_size)
{
    const float* enc  = (const float*)d_in[0];   // (16,2048,1024)
    const float* W    = (const float*)d_in[1];   // (8,1024,3)
    const float* bias = (const float*)d_in[2];   // (8,3)
    const int*   head = (const int*)d_in[3];     // (16,32)
    const int*   tail = (const int*)d_in[4];     // (16,32)
    const int*   cls  = (const int*)d_in[5];     // (16,32)
    const int*   lab  = (const int*)d_in[6];     // (16,32)
    float* out = (float*)d_out;

    int write_loss = (out_size > NSPAN * NLBL) ? 1 : 0;
    fused_kernel<<<NGRID, 256>>>(enc, W, bias, head, tail, cls, lab, out, write_loss);
}

// round 8
// speedup vs baseline: 1.1787x; 1.1787x over previous
#include <cuda_runtime.h>
#include <math.h>

#define BSZ 16
#define SEQ 2048
#define HID 1024
#define NSP_PER_B 32
#define NCLS 8
#define NLBL 3
#define NSPAN (BSZ * NSP_PER_B)   // 512
#define H4 (HID / 4)              // 256

// Packed accumulator: bits[0:10) arrivals, bits[10:20) valid count,
// bits[20:64) fixed-point (2^30) NLL sum. Relaxed atomics only; the RMW
// return value carries all cross-CTA data, so no fences are needed.
__device__ unsigned long long g_acc = 0ULL;   // reset by last CTA each launch

#define FIX_SHIFT 20
#define VALID_SHIFT 10
#define ARRIVE_MASK 0x3FFULL
#define FIX_SCALE 1073741824.0   // 2^30

// One CTA per span: mean-pool rows [head+1, tail) over H, dot with W[c], add
// bias -> 3 logits; local NLL folded into one relaxed packed atomicAdd.
__global__ __launch_bounds__(256, 4)
void fused_kernel(const float* __restrict__ enc,
                  const float* __restrict__ W,
                  const float* __restrict__ bias,
                  const int* __restrict__ head,
                  const int* __restrict__ tail,
                  const int* __restrict__ cls,
                  const int* __restrict__ labels,
                  float* __restrict__ out,       // [NSPAN*NLBL] logits, then loss
                  int write_loss)
{
    const int span = blockIdx.x;            // 0..511
    const int b    = span / NSP_PER_B;
    const int s0   = head[span] + 1;
    const int n    = tail[span] - s0;       // span length (63 here)
    const int c    = cls[span];
    const int tid  = threadIdx.x;           // 256 threads, 1 float4 col each

    const float4* base = reinterpret_cast<const float4*>(enc)
                       + ((long)b * SEQ + s0) * H4 + tid;

    // R1-proven loop: 4 independent accumulators, unroll 4.
    float4 a0 = make_float4(0.f, 0.f, 0.f, 0.f);
    float4 a1 = a0, a2 = a0, a3 = a0;
    int s = 0;
    for (; s + 4 <= n; s += 4) {
        float4 v0 = base[(s + 0) * H4];
        float4 v1 = base[(s + 1) * H4];
        float4 v2 = base[(s + 2) * H4];
        float4 v3 = base[(s + 3) * H4];
        a0.x += v0.x; a0.y += v0.y; a0.z += v0.z; a0.w += v0.w;
        a1.x += v1.x; a1.y += v1.y; a1.z += v1.z; a1.w += v1.w;
        a2.x += v2.x; a2.y += v2.y; a2.z += v2.z; a2.w += v2.w;
        a3.x += v3.x; a3.y += v3.y; a3.z += v3.z; a3.w += v3.w;
    }
    for (; s < n; ++s) {
        float4 v = base[s * H4];
        a0.x += v.x; a0.y += v.y; a0.z += v.z; a0.w += v.w;
    }
    float4 acc;
    acc.x = (a0.x + a1.x) + (a2.x + a3.x);
    acc.y = (a0.y + a1.y) + (a2.y + a3.y);
    acc.z = (a0.z + a1.z) + (a2.z + a3.z);
    acc.w = (a0.w + a1.w) + (a2.w + a3.w);

    // W is (C, H, L): this thread's 4 H-cols are 12 contiguous floats.
    const float4* w4 = reinterpret_cast<const float4*>(W + (long)c * HID * NLBL)
                     + tid * 3;
    float4 w0 = w4[0], w1 = w4[1], w2 = w4[2];
    float p0 = acc.x * w0.x + acc.y * w0.w + acc.z * w1.z + acc.w * w2.y;
    float p1 = acc.x * w0.y + acc.y * w1.x + acc.z * w1.w + acc.w * w2.z;
    float p2 = acc.x * w0.z + acc.y * w1.y + acc.z * w2.x + acc.w * w2.w;

    #pragma unroll
    for (int off = 16; off > 0; off >>= 1) {
        p0 += __shfl_down_sync(0xffffffffu, p0, off);
        p1 += __shfl_down_sync(0xffffffffu, p1, off);
        p2 += __shfl_down_sync(0xffffffffu, p2, off);
    }
    __shared__ float sm[3][8];
    const int warp = tid >> 5, lane = tid & 31;
    if (lane == 0) { sm[0][warp] = p0; sm[1][warp] = p1; sm[2][warp] = p2; }
    __syncthreads();

    if (tid != 0) return;   // tail is a single-thread job; no further block sync

    float t0 = 0.f, t1 = 0.f, t2 = 0.f;
    #pragma unroll
    for (int w = 0; w < 8; ++w) { t0 += sm[0][w]; t1 += sm[1][w]; t2 += sm[2][w]; }
    float inv = 1.0f / (float)n;
    float l0 = t0 * inv + bias[c * NLBL + 0];
    float l1 = t1 * inv + bias[c * NLBL + 1];
    float l2 = t2 * inv + bias[c * NLBL + 2];
    out[span * NLBL + 0] = l0;
    out[span * NLBL + 1] = l1;
    out[span * NLBL + 2] = l2;

    if (!write_loss) return;

    // Local, deterministic NLL for this span (nll >= 0 always).
    int lab = labels[span];
    unsigned long long contrib = 1ULL;          // arrival ticket
    if (lab >= 0) {
        float mx  = fmaxf(l0, fmaxf(l1, l2));
        float lse = mx + logf(expf(l0 - mx) + expf(l1 - mx) + expf(l2 - mx));
        float lv  = (lab == 0) ? l0 : ((lab == 1) ? l1 : l2);
        double nll = (double)(lse - lv);
        unsigned long long fix = (unsigned long long)(nll * FIX_SCALE + 0.5);
        contrib |= (fix << FIX_SHIFT) | (1ULL << VALID_SHIFT);
    }

    // Single relaxed 64-bit RMW: carries sum, valid count, and arrival ticket.
    unsigned long long old = atomicAdd(&g_acc, contrib);
    if ((old & ARRIVE_MASK) == (unsigned long long)(NSPAN - 1)) {
        unsigned long long total = old + contrib;    // includes all 512 CTAs
        double sum   = (double)(total >> FIX_SHIFT) / FIX_SCALE;
        double valid = (double)((total >> VALID_SHIFT) & ARRIVE_MASK);
        out[NSPAN * NLBL] = (float)(sum / valid);
        g_acc = 0ULL;                                // reset for next replay
    }
}

extern "C" void kernel_launch(void* const* d_in, const int* in_sizes, int n_in,
                              void* d_out, int out_size)
{
    const float* enc  = (const float*)d_in[0];   // (16,2048,1024)
    const float* W    = (const float*)d_in[1];   // (8,1024,3)
    const float* bias = (const float*)d_in[2];   // (8,3)
    const int*   head = (const int*)d_in[3];     // (16,32)
    const int*   tail = (const int*)d_in[4];     // (16,32)
    const int*   cls  = (const int*)d_in[5];     // (16,32)
    const int*   lab  = (const int*)d_in[6];     // (16,32)
    float* out = (float*)d_out;

    int write_loss = (out_size > NSPAN * NLBL) ? 1 : 0;
    fused_kernel<<<NSPAN, 256>>>(enc, W, bias, head, tail, cls, lab, out, write_loss);
}